// round 12
// baseline (speedup 1.0000x reference)
#include <cuda_runtime.h>
#include <cuda_fp16.h>

// IVPLoss: 8-step Euler trajectories of bilinear-sampled vector fields,
// MSE between pred and true trajectories (incl. identity step 0).
//
// R12: FUSED producer/consumer kernel. 1D grid, per batch b:
//   [2311 repack blocks (pack batch b)] then [2304 traj blocks (batch b)].
// traj blocks spin on g_ready[b] (volatile L2 poll + nanosleep) until all
// repack blocks of their batch signalled (threadfence + atomicAdd).
// Overlap: traj(b) runs concurrently with repack(b+1..) — DRAM-bound
// repack hides under L1-bound traj. Dispatch is bid-ordered, producers
// precede consumers -> no starvation. finalize resets g_acc/g_ready so
// every graph replay starts clean (statics zero-init the first call).
//
// Packed layout per pixel (8B): { half2(c0[x],c1[x]), half2(c0[x+1],c1[x+1]) }
// padded col 768 = col 767, padded row 768 = row 767 ->
// one bilinear sample = 2 coalesced LDG.64 + HFMA2 lerps, no y+1 clamp.

#define Bv 8
#define Hv 768
#define Wv 768
#define WPK 769
#define HPK 769
#define NSTEPS 8
#define DXC 0.5f

#define PLANE (Hv * Wv)              // 589824
#define PK_PLANE (HPK * WPK)         // 591361
#define PK_TOTAL (Bv * PK_PLANE)

#define RP_BLKS 2311                 // ceil(PK_PLANE/256)
#define TJ_BLKS (Hv * 3)             // 2304 (3 x-segments per row)
#define BATCH_BLKS (RP_BLKS + TJ_BLKS)

__device__ uint2 g_pred[PK_TOTAL];
__device__ uint2 g_true[PK_TOTAL];
__device__ double g_acc;                    // zero-init; finalize resets
__device__ unsigned int g_ready[Bv];        // zero-init; finalize resets

__device__ __forceinline__ unsigned int h2u(__half2 h) {
    return *reinterpret_cast<unsigned int*>(&h);
}

__device__ __forceinline__ uint2 pack_pair(const float* __restrict__ f,
                                           int base, int xs, int x1) {
    __half2 p0 = __floats2half2_rn(__ldg(f + base + xs),
                                   __ldg(f + base + PLANE + xs));
    __half2 p1 = __floats2half2_rn(__ldg(f + base + x1),
                                   __ldg(f + base + PLANE + x1));
    return make_uint2(h2u(p0), h2u(p1));
}

__device__ __forceinline__ float2 bsample(const uint2* __restrict__ P,
                                          float x, float y) {
    // clip to [0, W-1] / [0, H-1] (matches jnp.clip)
    x = fminf(fmaxf(x, 0.0f), (float)(Wv - 1));
    y = fminf(fmaxf(y, 0.0f), (float)(Hv - 1));
    float xf = floorf(x);
    float yf = floorf(y);
    int xi = (int)xf;
    int yi = (int)yf;
    __half2 wx2 = __float2half2_rn(x - xf);
    __half2 wy2 = __float2half2_rn(y - yf);

    int ofs = yi * WPK + xi;
    uint2 r0 = __ldg(P + ofs);
    uint2 r1 = __ldg(P + ofs + WPK);    // padded bottom row: always valid
    __half2 v00 = *reinterpret_cast<__half2*>(&r0.x);
    __half2 v01 = *reinterpret_cast<__half2*>(&r0.y);
    __half2 v10 = *reinterpret_cast<__half2*>(&r1.x);
    __half2 v11 = *reinterpret_cast<__half2*>(&r1.y);

    __half2 top = __hfma2(wx2, __hsub2(v01, v00), v00);
    __half2 bot = __hfma2(wx2, __hsub2(v11, v10), v10);
    __half2 res = __hfma2(wy2, __hsub2(bot, top), top);
    return __half22float2(res);
}

__global__ __launch_bounds__(256) void fused_kernel(const float* __restrict__ pred,
                                                    const float* __restrict__ tru) {
    int bid = blockIdx.x;
    int b = bid / BATCH_BLKS;
    int r = bid - b * BATCH_BLKS;
    int tid = threadIdx.x;

    if (r < RP_BLKS) {
        // ---------------- producer: repack one 256-element slice of batch b
        int idx = r * 256 + tid;                  // within-batch element
        if (idx < PK_PLANE) {
            int x = idx % WPK;
            int y = idx / WPK;
            int xs = min(x, Wv - 1);              // pad col dups last col
            int x1 = min(xs + 1, Wv - 1);
            int ys = min(y, Hv - 1);              // pad row dups last row
            int base = b * 2 * PLANE + ys * Wv;   // channel-0 row base
            int dst = b * PK_PLANE + idx;
            g_pred[dst] = pack_pair(pred, base, xs, x1);
            g_true[dst] = pack_pair(tru,  base, xs, x1);
        }
        __syncthreads();
        __threadfence();                          // publish packed data
        if (tid == 0) atomicAdd(&g_ready[b], 1u);
        return;
    }

    // ---------------- consumer: one traj tile of batch b
    int t = r - RP_BLKS;                          // 0..2303
    int y = t / 3;
    int x = (t - y * 3) * 256 + tid;              // 0..767

    if (tid == 0) {
        const volatile unsigned int* flag = &g_ready[b];
        while (*flag < (unsigned int)RP_BLKS) __nanosleep(256);
    }
    __syncthreads();
    __threadfence();                              // acquire packed data

    const uint2* __restrict__ Pp = g_pred + b * PK_PLANE;
    const uint2* __restrict__ Pt = g_true + b * PK_PLANE;

    float pxp = (float)x, pyp = (float)y;
    float pxt = (float)x, pyt = (float)y;
    float acc = 0.0f;

    // step 0: exact integer position -> bilinear == v00 (bit-exact)
    {
        int ofs0 = y * WPK + x;
        unsigned int wp = __ldg(reinterpret_cast<const unsigned int*>(Pp) + 2 * ofs0);
        unsigned int wt = __ldg(reinterpret_cast<const unsigned int*>(Pt) + 2 * ofs0);
        float2 vp = __half22float2(*reinterpret_cast<__half2*>(&wp));
        float2 vt = __half22float2(*reinterpret_cast<__half2*>(&wt));
        pxp = fmaf(DXC, vp.x, pxp);
        pyp = fmaf(DXC, vp.y, pyp);
        pxt = fmaf(DXC, vt.x, pxt);
        pyt = fmaf(DXC, vt.y, pyt);
        float dx = pxt - pxp;
        float dy = pyt - pyp;
        acc = fmaf(dx, dx, acc);
        acc = fmaf(dy, dy, acc);
    }

    #pragma unroll
    for (int s = 1; s < NSTEPS; s++) {
        float2 vp = bsample(Pp, pxp, pyp);
        float2 vt = bsample(Pt, pxt, pyt);
        pxp = fmaf(DXC, vp.x, pxp);
        pyp = fmaf(DXC, vp.y, pyp);
        pxt = fmaf(DXC, vt.x, pxt);
        pyt = fmaf(DXC, vt.y, pyt);
        float dx = pxt - pxp;
        float dy = pyt - pyp;
        acc = fmaf(dx, dx, acc);
        acc = fmaf(dy, dy, acc);
    }

    // block reduction: warp shuffle -> shared -> warp0 -> atomicAdd(double)
    float v = acc;
    #pragma unroll
    for (int o = 16; o > 0; o >>= 1)
        v += __shfl_down_sync(0xffffffffu, v, o);

    __shared__ float sred[8];
    int lane = threadIdx.x & 31;
    int wid  = threadIdx.x >> 5;
    if (lane == 0) sred[wid] = v;
    __syncthreads();
    if (wid == 0) {
        v = (lane < 8) ? sred[lane] : 0.0f;
        #pragma unroll
        for (int o = 4; o > 0; o >>= 1)
            v += __shfl_down_sync(0xffffffffu, v, o);
        if (lane == 0) atomicAdd(&g_acc, (double)v);
    }
}

__global__ void finalize_kernel(float* __restrict__ out) {
    const double cnt = (double)(NSTEPS + 1) * Bv * 2 * Hv * Wv;  // 84934656
    *out = (float)(g_acc / cnt);
    g_acc = 0.0;                                  // reset for next replay
    #pragma unroll
    for (int b = 0; b < Bv; b++) g_ready[b] = 0u;
}

extern "C" void kernel_launch(void* const* d_in, const int* in_sizes, int n_in,
                              void* d_out, int out_size) {
    const float* vf_pred = (const float*)d_in[0];
    const float* vf_true = (const float*)d_in[1];
    float* out = (float*)d_out;

    fused_kernel<<<Bv * BATCH_BLKS, 256>>>(vf_pred, vf_true);
    finalize_kernel<<<1, 1>>>(out);
}

// round 13
// speedup vs baseline: 1.2691x; 1.2691x over previous
#include <cuda_runtime.h>
#include <cuda_fp16.h>

// IVPLoss: 8-step Euler trajectories of bilinear-sampled vector fields,
// MSE between pred and true trajectories (incl. identity step 0).
//
// R13 = R9 kernel bodies (best: 115.3us), restructured as a per-batch
// two-stream pipeline using the graph-capture fork/join pattern:
//   default stream: repack(0) .. repack(7)   (DRAM-bound)
//   stream s2:      traj(b) waits event(repack(b))   (L1-bound)
// repack(b+1..) overlaps traj(0..b) on complementary pipes. finalize
// joins s2 back into the capture stream. R12 showed in-kernel spinning
// can't do this (consumers occupy waves); streams + events can.
//
// Packed layout per pixel (8B): { half2(c0[x],c1[x]), half2(c0[x+1],c1[x+1]) }
// padded col 768 = col 767, padded row 768 = row 767 ->
// one bilinear sample = 2 coalesced LDG.64 + HFMA2 lerps, no y+1 clamp.

#define Bv 8
#define Hv 768
#define Wv 768
#define WPK 769
#define HPK 769
#define NSTEPS 8
#define DXC 0.5f

#define PLANE (Hv * Wv)              // 589824
#define PK_PLANE (HPK * WPK)         // 591361
#define PK_TOTAL (Bv * PK_PLANE)

#define RP_BLKS ((PK_PLANE + 255) / 256)   // 2311

__device__ uint2 g_pred[PK_TOTAL];
__device__ uint2 g_true[PK_TOTAL];
__device__ double g_acc;

__device__ __forceinline__ unsigned int h2u(__half2 h) {
    return *reinterpret_cast<unsigned int*>(&h);
}

__device__ __forceinline__ uint2 pack_pair(const float* __restrict__ f,
                                           int base, int xs, int x1) {
    __half2 p0 = __floats2half2_rn(__ldg(f + base + xs),
                                   __ldg(f + base + PLANE + xs));
    __half2 p1 = __floats2half2_rn(__ldg(f + base + x1),
                                   __ldg(f + base + PLANE + x1));
    return make_uint2(h2u(p0), h2u(p1));
}

// per-batch repack (R2/R9 per-pixel structure; best measured)
__global__ __launch_bounds__(256) void repack_kernel(const float* __restrict__ pred,
                                                     const float* __restrict__ tru,
                                                     int b) {
    int idx = blockIdx.x * blockDim.x + threadIdx.x;   // element within batch
    if (idx == 0 && b == 0) g_acc = 0.0;               // reset before any traj
    if (idx >= PK_PLANE) return;
    int x = idx % WPK;
    int y = idx / WPK;
    int xs = min(x, Wv - 1);                 // padded col duplicates last col
    int x1 = min(xs + 1, Wv - 1);
    int ys = min(y, Hv - 1);                 // padded row duplicates last row
    int base = b * 2 * PLANE + ys * Wv;      // channel-0 row base
    int dst = b * PK_PLANE + idx;
    g_pred[dst] = pack_pair(pred, base, xs, x1);
    g_true[dst] = pack_pair(tru,  base, xs, x1);
}

__device__ __forceinline__ float2 bsample(const uint2* __restrict__ P,
                                          float x, float y) {
    // clip to [0, W-1] / [0, H-1] (matches jnp.clip)
    x = fminf(fmaxf(x, 0.0f), (float)(Wv - 1));
    y = fminf(fmaxf(y, 0.0f), (float)(Hv - 1));
    float xf = floorf(x);
    float yf = floorf(y);
    int xi = (int)xf;
    int yi = (int)yf;
    __half2 wx2 = __float2half2_rn(x - xf);
    __half2 wy2 = __float2half2_rn(y - yf);

    int ofs = yi * WPK + xi;
    uint2 r0 = __ldg(P + ofs);
    uint2 r1 = __ldg(P + ofs + WPK);    // padded bottom row: always valid
    __half2 v00 = *reinterpret_cast<__half2*>(&r0.x);
    __half2 v01 = *reinterpret_cast<__half2*>(&r0.y);
    __half2 v10 = *reinterpret_cast<__half2*>(&r1.x);
    __half2 v11 = *reinterpret_cast<__half2*>(&r1.y);

    __half2 top = __hfma2(wx2, __hsub2(v01, v00), v00);
    __half2 bot = __hfma2(wx2, __hsub2(v11, v10), v10);
    __half2 res = __hfma2(wy2, __hsub2(bot, top), top);
    return __half22float2(res);
}

// per-batch trajectory + MSE partial; grid (3, 768)
__global__ __launch_bounds__(256) void traj_kernel(int b) {
    int x = blockIdx.x * blockDim.x + threadIdx.x;  // 0..767
    int y = blockIdx.y;
    const uint2* __restrict__ Pp = g_pred + b * PK_PLANE;
    const uint2* __restrict__ Pt = g_true + b * PK_PLANE;

    float pxp = (float)x, pyp = (float)y;   // pred trajectory
    float pxt = (float)x, pyt = (float)y;   // true trajectory
    float acc = 0.0f;

    #pragma unroll
    for (int s = 0; s < NSTEPS; s++) {
        float2 vp = bsample(Pp, pxp, pyp);
        float2 vt = bsample(Pt, pxt, pyt);
        pxp = fmaf(DXC, vp.x, pxp);
        pyp = fmaf(DXC, vp.y, pyp);
        pxt = fmaf(DXC, vt.x, pxt);
        pyt = fmaf(DXC, vt.y, pyt);
        float dx = pxt - pxp;
        float dy = pyt - pyp;
        acc = fmaf(dx, dx, acc);
        acc = fmaf(dy, dy, acc);
    }

    // block reduction: warp shuffle -> shared -> warp0 -> atomicAdd(double)
    float v = acc;
    #pragma unroll
    for (int o = 16; o > 0; o >>= 1)
        v += __shfl_down_sync(0xffffffffu, v, o);

    __shared__ float sred[8];
    int lane = threadIdx.x & 31;
    int wid  = threadIdx.x >> 5;
    if (lane == 0) sred[wid] = v;
    __syncthreads();
    if (wid == 0) {
        v = (lane < 8) ? sred[lane] : 0.0f;
        #pragma unroll
        for (int o = 4; o > 0; o >>= 1)
            v += __shfl_down_sync(0xffffffffu, v, o);
        if (lane == 0) atomicAdd(&g_acc, (double)v);
    }
}

__global__ void finalize_kernel(float* __restrict__ out) {
    const double cnt = (double)(NSTEPS + 1) * Bv * 2 * Hv * Wv;  // 84934656
    *out = (float)(g_acc / cnt);
}

extern "C" void kernel_launch(void* const* d_in, const int* in_sizes, int n_in,
                              void* d_out, int out_size) {
    const float* vf_pred = (const float*)d_in[0];
    const float* vf_true = (const float*)d_in[1];
    float* out = (float*)d_out;

    // fork/join two-stream pipeline (graph-capture-safe pattern; no device
    // memory is allocated — streams/events are host-side objects, created
    // on each of the few host invocations and intentionally not destroyed
    // because destruction during an active capture is illegal).
    cudaStream_t s2;
    cudaStreamCreateWithFlags(&s2, cudaStreamNonBlocking);
    cudaEvent_t evFork, evJoin, evR[Bv];
    cudaEventCreateWithFlags(&evFork, cudaEventDisableTiming);
    cudaEventCreateWithFlags(&evJoin, cudaEventDisableTiming);
    for (int b = 0; b < Bv; b++)
        cudaEventCreateWithFlags(&evR[b], cudaEventDisableTiming);

    cudaEventRecord(evFork, 0);
    cudaStreamWaitEvent(s2, evFork, 0);          // fork s2 from capture stream

    dim3 tj_grid(Wv / 256, Hv);
    for (int b = 0; b < Bv; b++) {
        repack_kernel<<<RP_BLKS, 256>>>(vf_pred, vf_true, b);
        cudaEventRecord(evR[b], 0);
        cudaStreamWaitEvent(s2, evR[b], 0);
        traj_kernel<<<tj_grid, 256, 0, s2>>>(b);
    }

    cudaEventRecord(evJoin, s2);
    cudaStreamWaitEvent(0, evJoin, 0);           // join s2 back
    finalize_kernel<<<1, 1>>>(out);
}